// round 17
// baseline (speedup 1.0000x reference)
#include <cuda_runtime.h>
#include <mma.h>
#include <cstdint>

using namespace nvcuda;

#define NNODES 50000
#define MPAD   50048
#define FDIM   128
#define KNB    32
#define EDIM   16
#define KK     2048          // FDIM * EDIM

__device__ float g_buf[(size_t)MPAD * KK];   // [i][l*16+n], pad rows stay 0
__device__ float W2[KK * FDIM];              // [k=(l*16+n)][m]
__device__ int   g_nlist_is64;

// ---------------------------------------------------------------------------
__global__ void detect_nlist(const int* __restrict__ nl) {
    int odd_or = 0;
#pragma unroll
    for (int t = 1; t < 64; t += 2) odd_or |= nl[t];
    g_nlist_is64 = (odd_or == 0) ? 1 : 0;
}

// W2[(l*16+n)*128 + m] = tf32(w[l,m,n])
__global__ void build_w2(const float* __restrict__ w) {
    int idx = blockIdx.x * 256 + threadIdx.x;
    if (idx < KK * FDIM) {
        int m = idx & (FDIM - 1);
        int k = idx >> 7;
        int l = k >> 4;
        int n = k & (EDIM - 1);
        W2[idx] = wmma::__float_to_tf32(w[(size_t)l * FDIM * EDIM + (size_t)m * EDIM + n]);
    }
}

// ---------------------------------------------------------------------------
__device__ __forceinline__ void cp16(void* s, const void* g) {
    uint32_t sa = (uint32_t)__cvta_generic_to_shared(s);
    asm volatile("cp.async.cg.shared.global [%0], [%1], 16;\n" :: "r"(sa), "l"(g));
}
__device__ __forceinline__ void cp_commit() { asm volatile("cp.async.commit_group;\n"); }
template <int N>
__device__ __forceinline__ void cp_wait() { asm volatile("cp.async.wait_group %0;\n" :: "n"(N)); }

// ---------------------------------------------------------------------------
// Stage 1 (2-D mapping, duplicated-e smem, FFMA2, fp32-exact):
//   thread (lq, nq): lq = tid>>2 (4 l-values), nq = tid&3 (4 n-values)
//   acc[p][n] (f32x2 over l-pair p) += vpair[p] * dup(e[j][n])
// Per j: 1 LDG.128 (v, MLP-8) + 1 LDS(idx) + 2 ld.shared.v2.u64 (dup e)
//        + 8 fma.rn.f32x2.
// ---------------------------------------------------------------------------
__global__ __launch_bounds__(128) void gather_contract(const float* __restrict__ nodes,
                                                       const int* __restrict__ nlist32,
                                                       const float* __restrict__ edges) {
    const int i   = blockIdx.x;
    const int tid = threadIdx.x;
    const int nq  = tid & 3;        // n quarter (4 n-values)
    const int lq  = tid >> 2;       // l block of 4

    __shared__ __align__(16) unsigned long long se2[KNB * EDIM];  // dup'd e, 4KB
    __shared__ int snb[KNB];

    // Build duplicated edge table: se2[j*16+n] = {e, e}
    {
        float4 e4 = ((const float4*)(edges + (size_t)i * KNB * EDIM))[tid];
        unsigned long long d0, d1, d2, d3;
        asm("mov.b64 %0, {%1, %1};" : "=l"(d0) : "f"(e4.x));
        asm("mov.b64 %0, {%1, %1};" : "=l"(d1) : "f"(e4.y));
        asm("mov.b64 %0, {%1, %1};" : "=l"(d2) : "f"(e4.z));
        asm("mov.b64 %0, {%1, %1};" : "=l"(d3) : "f"(e4.w));
        ulonglong2* p = (ulonglong2*)&se2[tid * 4];
        p[0] = make_ulonglong2(d0, d1);
        p[1] = make_ulonglong2(d2, d3);
    }
    if (tid < KNB) {
        int pos = i * KNB + tid;
        int idx = g_nlist_is64 ? nlist32[2 * (size_t)pos] : nlist32[pos];
        idx = idx < 0 ? 0 : (idx >= NNODES ? NNODES - 1 : idx);
        snb[tid] = idx;
    }
    __syncthreads();

    unsigned long long acc[2][4];
#pragma unroll
    for (int p = 0; p < 2; p++)
#pragma unroll
        for (int n = 0; n < 4; n++) acc[p][n] = 0ULL;

    const uint32_t se_base = (uint32_t)__cvta_generic_to_shared(se2) + nq * 32;

#pragma unroll 8
    for (int j = 0; j < KNB; j++) {
        // v: 4 l-values as 2 f32x2 pairs (16B coalescible, L2-resident)
        ulonglong2 v2 = __ldg((const ulonglong2*)(nodes + (size_t)snb[j] * FDIM + lq * 4));
        unsigned long long e0, e1, e2, e3;
        uint32_t ja = se_base + j * 128;
        asm("ld.shared.v2.u64 {%0, %1}, [%2];" : "=l"(e0), "=l"(e1) : "r"(ja));
        asm("ld.shared.v2.u64 {%0, %1}, [%2];" : "=l"(e2), "=l"(e3) : "r"(ja + 16));
        asm("fma.rn.f32x2 %0, %1, %2, %3;" : "=l"(acc[0][0]) : "l"(v2.x), "l"(e0), "l"(acc[0][0]));
        asm("fma.rn.f32x2 %0, %1, %2, %3;" : "=l"(acc[0][1]) : "l"(v2.x), "l"(e1), "l"(acc[0][1]));
        asm("fma.rn.f32x2 %0, %1, %2, %3;" : "=l"(acc[0][2]) : "l"(v2.x), "l"(e2), "l"(acc[0][2]));
        asm("fma.rn.f32x2 %0, %1, %2, %3;" : "=l"(acc[0][3]) : "l"(v2.x), "l"(e3), "l"(acc[0][3]));
        asm("fma.rn.f32x2 %0, %1, %2, %3;" : "=l"(acc[1][0]) : "l"(v2.y), "l"(e0), "l"(acc[1][0]));
        asm("fma.rn.f32x2 %0, %1, %2, %3;" : "=l"(acc[1][1]) : "l"(v2.y), "l"(e1), "l"(acc[1][1]));
        asm("fma.rn.f32x2 %0, %1, %2, %3;" : "=l"(acc[1][2]) : "l"(v2.y), "l"(e2), "l"(acc[1][2]));
        asm("fma.rn.f32x2 %0, %1, %2, %3;" : "=l"(acc[1][3]) : "l"(v2.y), "l"(e3), "l"(acc[1][3]));
    }

    // Unpack: acc[p][n] = (out[l=lq*4+2p, n'], out[l=lq*4+2p+1, n']), n' = nq*4+n
    float r[4][4];   // r[li][n]
#pragma unroll
    for (int p = 0; p < 2; p++)
#pragma unroll
        for (int n = 0; n < 4; n++) {
            float lo, hi;
            asm("mov.b64 {%0, %1}, %2;" : "=f"(lo), "=f"(hi) : "l"(acc[p][n]));
            r[2 * p][n]     = wmma::__float_to_tf32(lo);
            r[2 * p + 1][n] = wmma::__float_to_tf32(hi);
        }

    float* grow = g_buf + (size_t)i * KK + nq * 4;
#pragma unroll
    for (int li = 0; li < 4; li++)
        *(float4*)(grow + (size_t)(lq * 4 + li) * EDIM) =
            make_float4(r[li][0], r[li][1], r[li][2], r[li][3]);
}

// ---------------------------------------------------------------------------
// Stage 2: C = (1/32) * g_buf @ W2  (M=50048, N=128, K=2048), tf32 wmma.
// BM=128, BN=128, BK=32, 3-stage cp.async ring, 1 sync/iter, 64 iters.
// (unchanged — measured 388us)
// ---------------------------------------------------------------------------
#define BK2        32
#define STAGES     3
#define AS_STRIDE  36
#define AS_BYTES   (128 * AS_STRIDE * 4)       // 18432
#define BS_STRIDE  132
#define BS_BYTES   (BK2 * BS_STRIDE * 4)       // 16896
#define STAGE_BYTES (AS_BYTES + BS_BYTES)      // 35328
#define S2_SMEM    (STAGES * STAGE_BYTES)      // 105984

__global__ __launch_bounds__(256, 2) void gemm_tf32(float* __restrict__ out) {
    extern __shared__ __align__(16) char s2mem[];

    const int tid = threadIdx.x;
    const int wid = tid >> 5;
    const int warp_m = wid >> 1;   // 0..3
    const int warp_n = wid & 1;    // 0..1
    const size_t row0 = (size_t)blockIdx.x * 128;

    auto Asm = [&](int s) -> float* { return (float*)(s2mem + s * STAGE_BYTES); };
    auto Bsm = [&](int s) -> float* { return (float*)(s2mem + s * STAGE_BYTES + AS_BYTES); };

    wmma::fragment<wmma::accumulator, 16, 16, 8, float> c[2][4];
#pragma unroll
    for (int mi = 0; mi < 2; mi++)
#pragma unroll
        for (int ni = 0; ni < 4; ni++) wmma::fill_fragment(c[mi][ni], 0.0f);

    auto load_tiles = [&](int s, int kb) {
        const float* Ab = g_buf + row0 * KK + (size_t)(kb * BK2);
        const float* Bb = W2 + (size_t)(kb * BK2) * FDIM;
        float* A = Asm(s);
        float* B = Bsm(s);
#pragma unroll
        for (int u = 0; u < 4; u++) {          // A: 128 x 32 -> 1024 float4
            int q = tid + u * 256;
            int ar = q >> 3, ac = q & 7;
            cp16(A + ar * AS_STRIDE + ac * 4, Ab + (size_t)ar * KK + ac * 4);
        }
#pragma unroll
        for (int u = 0; u < 4; u++) {          // B: 32 x 128 -> 1024 float4
            int q = tid + u * 256;
            int br = q >> 5, bc = q & 31;
            cp16(B + br * BS_STRIDE + bc * 4, Bb + br * FDIM + bc * 4);
        }
        cp_commit();
    };

    load_tiles(0, 0);
    load_tiles(1, 1);

    const int nkb = KK / BK2;  // 64
    for (int kb = 0; kb < nkb; kb++) {
        int cur = kb % STAGES;

        if (kb + 1 < nkb) cp_wait<1>();
        else              cp_wait<0>();
        __syncthreads();

        if (kb + 2 < nkb) load_tiles((kb + 2) % STAGES, kb + 2);

        const float* A = Asm(cur);
        const float* B = Bsm(cur);
#pragma unroll
        for (int kk = 0; kk < 4; kk++) {
            wmma::fragment<wmma::matrix_a, 16, 16, 8, wmma::precision::tf32, wmma::row_major> a[2];
            wmma::fragment<wmma::matrix_b, 16, 16, 8, wmma::precision::tf32, wmma::row_major> b[4];
#pragma unroll
            for (int mi = 0; mi < 2; mi++)
                wmma::load_matrix_sync(a[mi],
                    A + (warp_m * 32 + mi * 16) * AS_STRIDE + kk * 8, AS_STRIDE);
#pragma unroll
            for (int ni = 0; ni < 4; ni++)
                wmma::load_matrix_sync(b[ni],
                    B + (kk * 8) * BS_STRIDE + warp_n * 64 + ni * 16, BS_STRIDE);
#pragma unroll
            for (int mi = 0; mi < 2; mi++)
#pragma unroll
                for (int ni = 0; ni < 4; ni++)
                    wmma::mma_sync(c[mi][ni], a[mi], b[ni], c[mi][ni]);
        }
    }

    const float scale = 1.0f / (float)KNB;
#pragma unroll
    for (int mi = 0; mi < 2; mi++)
#pragma unroll
        for (int ni = 0; ni < 4; ni++) {
#pragma unroll
            for (int t = 0; t < c[mi][ni].num_elements; t++) c[mi][ni].x[t] *= scale;
            size_t rglob = row0 + warp_m * 32 + mi * 16;
            if (rglob < NNODES)   // 16-row fragments fully valid (80 % 16 == 0)
                wmma::store_matrix_sync(out + rglob * FDIM + warp_n * 64 + ni * 16,
                                        c[mi][ni], FDIM, wmma::mem_row_major);
        }
}

// ---------------------------------------------------------------------------
extern "C" void kernel_launch(void* const* d_in, const int* in_sizes, int n_in,
                              void* d_out, int out_size) {
    const float* nodes = nullptr;
    const int*   nlist = nullptr;
    const float* edges = nullptr;
    const float* w     = nullptr;
    for (int t = 0; t < n_in; t++) {
        long long s = in_sizes[t];
        if      (s == (long long)NNODES * FDIM)        nodes = (const float*)d_in[t];
        else if (s == (long long)NNODES * KNB)         nlist = (const int*)d_in[t];
        else if (s == (long long)NNODES * KNB * EDIM)  edges = (const float*)d_in[t];
        else if (s == (long long)FDIM * FDIM * EDIM)   w     = (const float*)d_in[t];
    }
    if (!nodes) nodes = (const float*)d_in[0];
    if (!nlist) nlist = (const int*)d_in[1];
    if (!edges) edges = (const float*)d_in[2];
    if (!w)     w     = (const float*)d_in[3];

    float* out = (float*)d_out;

    static bool attr_done = false;
    if (!attr_done) {
        cudaFuncSetAttribute(gemm_tf32,
                             cudaFuncAttributeMaxDynamicSharedMemorySize, S2_SMEM);
        attr_done = true;
    }

    detect_nlist<<<1, 1>>>(nlist);
    build_w2<<<(KK * FDIM + 255) / 256, 256>>>(w);
    gather_contract<<<NNODES, 128>>>(nodes, nlist, edges);
    gemm_tf32<<<MPAD / 128, 256, S2_SMEM>>>(out);
}